// round 15
// baseline (speedup 1.0000x reference)
#include <cuda_runtime.h>
#include <cuda_bf16.h>
#include <math.h>
#include <cstdint>

#define BSN 2500
#define TT  400
#define DD  16
#define HH  32
#define G4  128

#define MTILES   20
#define KSLICES  7
#define KSL      368          // 7*368 = 2576 >= 2500
#define KCH      23           // K16 chunks per slice
#define KTPAD    376          // padded k stride in B stage
#define KPAD     2576         // global q^T k stride
#define NCTA     140
#define NTHREADS 512
#define LCTAS    125
#define ROWS     20
#define RPAD     2560         // padded rows in agg

// SMEM layout (bytes)
#define AFRAG_BYTES (8*KCH*32*16)              // 94208 (A_hi only)
#define SM_AHI   0
#define SM_BHI   AFRAG_BYTES                   // 94208
#define BST_BYTES (32*KTPAD*2)                 // 24064
#define SM_BLO   (SM_BHI + BST_BYTES)          // 118272
#define SM_G4S   (SM_BLO + BST_BYTES)          // 142336
#define SM_HS    (SM_G4S + ROWS*G4*4)          // 152576
#define SM_CS    (SM_HS + ROWS*HH*4)           // 155136
#define SM_XS    (SM_CS + ROWS*HH*4)           // 157696
#define SMEM_TOTAL (SM_XS + ROWS*DD*4 + 64)    // 159040

__device__ unsigned int g_bar;
__device__ __nv_bfloat16 g_qT_hi[32 * KPAD];
__device__ __nv_bfloat16 g_qT_lo[32 * KPAD];
__device__ uint4 g_alo[(size_t)NCTA * 8 * KCH * 32];   // A_lo fragments
__device__ float g_agg[(size_t)RPAD * 32];             // zero-init; invariant: zero at step start

#define MMA_BF16(d, a, b0_, b1_) \
    asm volatile("mma.sync.aligned.m16n8k16.row.col.f32.bf16.bf16.f32 " \
        "{%0,%1,%2,%3}, {%4,%5,%6,%7}, {%8,%9}, {%0,%1,%2,%3};" \
        : "+f"((d)[0]), "+f"((d)[1]), "+f"((d)[2]), "+f"((d)[3]) \
        : "r"((a).x), "r"((a).y), "r"((a).z), "r"((a).w), "r"(b0_), "r"(b1_))

__device__ __forceinline__ void red_add(float* p, float v) {
    asm volatile("red.global.add.f32 [%0], %1;" :: "l"(p), "f"(v) : "memory");
}
__device__ __forceinline__ void cp_async16(unsigned dst, const void* src) {
    asm volatile("cp.async.cg.shared.global [%0], [%1], 16;" :: "r"(dst), "l"(src) : "memory");
}
__device__ __forceinline__ float sigmoid_f(float x) {
    return __fdividef(1.0f, 1.0f + __expf(-x));
}
__device__ __forceinline__ float tanh_f(float x) {
    return 1.0f - __fdividef(2.0f, __expf(2.0f * x) + 1.0f);
}
__device__ __forceinline__ void st_u16_cg(__nv_bfloat16* p, unsigned short v) {
    asm volatile("st.global.cg.u16 [%0], %1;" :: "l"(p), "h"(v) : "memory");
}

__device__ __forceinline__ void grid_barrier(unsigned epoch) {
    __threadfence();
    __syncthreads();
    if (threadIdx.x == 0) {
        atomicAdd(&g_bar, 1u);
        const unsigned target = epoch * (unsigned)NCTA;
        unsigned v;
        do {
            asm volatile("ld.acquire.gpu.global.u32 %0, [%1];" : "=r"(v) : "l"(&g_bar) : "memory");
        } while (v < target);
    }
    __syncthreads();
}

__global__ void rgcn_reset() { g_bar = 0u; }

__device__ __forceinline__ void split_pair(const float* __restrict__ adj, int r, int k,
                                           uint32_t& h, uint32_t& l) {
    float xv = (r < BSN && k     < BSN) ? __ldg(&adj[(size_t)r * BSN + k])     : 0.0f;
    float yv = (r < BSN && k + 1 < BSN) ? __ldg(&adj[(size_t)r * BSN + k + 1]) : 0.0f;
    __nv_bfloat16 hx = __float2bfloat16(xv), hy = __float2bfloat16(yv);
    __nv_bfloat16 lx = __float2bfloat16(xv - __bfloat162float(hx));
    __nv_bfloat16 ly = __float2bfloat16(yv - __bfloat162float(hy));
    h = (uint32_t)__bfloat16_as_ushort(hx) | ((uint32_t)__bfloat16_as_ushort(hy) << 16);
    l = (uint32_t)__bfloat16_as_ushort(lx) | ((uint32_t)__bfloat16_as_ushort(ly) << 16);
}

// gates pre-activated into g4s (512 threads: 4 groups x 5 rows)
__device__ __forceinline__ void gates_act(
    int tid, const float* xs, const float* hs, float* g4s,
    const float* __restrict__ W_ih, const float* __restrict__ W_hh,
    const float* __restrict__ b)
{
    const int j  = tid & 127;
    const int m0 = (tid >> 7) * 5;
    float a5[5];
    const float bj = b[j];
    #pragma unroll
    for (int mm = 0; mm < 5; mm++) a5[mm] = bj;
    #pragma unroll
    for (int kk = 0; kk < HH; kk++) {
        const float w = W_hh[kk * G4 + j];
        #pragma unroll
        for (int mm = 0; mm < 5; mm++) a5[mm] += hs[(m0 + mm) * HH + kk] * w;
    }
    #pragma unroll
    for (int d = 0; d < DD; d++) {
        const float w = W_ih[d * G4 + j];
        #pragma unroll
        for (int mm = 0; mm < 5; mm++) a5[mm] += xs[(m0 + mm) * DD + d] * w;
    }
    const int sect = j >> 5;
    #pragma unroll
    for (int mm = 0; mm < 5; mm++) {
        const float v = (sect == 2) ? tanh_f(a5[mm]) : sigmoid_f(a5[mm]);
        g4s[(m0 + mm) * G4 + j] = v;
    }
}

__device__ __forceinline__ void q_prep(
    int tid, int row0, const float* hs,
    const float* __restrict__ W_q, const float* __restrict__ b_q)
{
    for (int e = tid; e < ROWS * HH; e += NTHREADS) {
        const int m = e >> 5, n = e & 31;
        float a = b_q[n];
        #pragma unroll
        for (int kk = 0; kk < HH; kk++) a += hs[m * HH + kk] * W_q[kk * HH + n];
        const float q = tanh_f(a);
        const __nv_bfloat16 hi = __float2bfloat16(q);
        const __nv_bfloat16 lo = __float2bfloat16(q - __bfloat162float(hi));
        const int r = row0 + m;
        st_u16_cg(&g_qT_hi[n * KPAD + r], __bfloat16_as_ushort(hi));
        st_u16_cg(&g_qT_lo[n * KPAD + r], __bfloat16_as_ushort(lo));
    }
}

__global__ void __launch_bounds__(NTHREADS, 1)
rgcn_kernel(const float* __restrict__ x,    const float* __restrict__ adj,
            const float* __restrict__ W_ih, const float* __restrict__ W_hh,
            const float* __restrict__ b,    const float* __restrict__ W_q,
            const float* __restrict__ b_q,  const float* __restrict__ W_d,
            const float* __restrict__ b_d,  float* __restrict__ out)
{
    extern __shared__ char smem[];
    float* g4s = (float*)(smem + SM_G4S);
    float* hs  = (float*)(smem + SM_HS);
    float* cs  = (float*)(smem + SM_CS);
    float* xs  = (float*)(smem + SM_XS);
    const unsigned smem_u = (unsigned)__cvta_generic_to_shared(smem);

    const int tid  = threadIdx.x;
    const int lane = tid & 31;
    const int wid  = tid >> 5;
    const int bid  = blockIdx.x;
    const int mtg  = bid / KSLICES;
    const int ksl  = bid % KSLICES;
    const bool lstm = (bid < LCTAS);
    const int row0 = bid * ROWS;
    const int g    = lane >> 2;
    const int tig  = lane & 3;
    const int msub  = wid & 7;
    const int khalf = wid >> 3;

    // ---- prologue: A_hi frags -> SMEM, A_lo frags -> global ----
    for (int idx = tid; idx < 8 * KCH * 32; idx += NTHREADS) {
        const int l  = idx & 31;
        const int c  = (idx >> 5) % KCH;
        const int mt = idx / (KCH * 32);
        const int lg = l >> 2, lt = l & 3;
        const int r0 = mtg * 128 + mt * 16 + lg;
        const int kb = ksl * KSL + c * 16 + lt * 2;
        uint32_t h0, h1, h2, h3, l0, l1, l2, l3;
        split_pair(adj, r0,     kb,     h0, l0);
        split_pair(adj, r0 + 8, kb,     h1, l1);
        split_pair(adj, r0,     kb + 8, h2, l2);
        split_pair(adj, r0 + 8, kb + 8, h3, l3);
        *(uint4*)(smem + SM_AHI + (size_t)idx * 16) = make_uint4(h0, h1, h2, h3);
        g_alo[(size_t)bid * (8 * KCH * 32) + idx] = make_uint4(l0, l1, l2, l3);
    }

    if (lstm) {
        for (int e = tid; e < ROWS * HH; e += NTHREADS) { hs[e] = 0.0f; cs[e] = 0.0f; }
        for (int e = tid; e < ROWS * DD; e += NTHREADS)
            xs[e] = x[(size_t)(row0 + e / DD) * (TT * DD) + (e & (DD - 1))];
    }
    __syncthreads();
    if (lstm) {
        gates_act(tid, xs, hs, g4s, W_ih, W_hh, b);
        q_prep(tid, row0, hs, W_q, b_q);
    }
    grid_barrier(1);

    const int cbeg = khalf ? 12 : 0;
    const int cend = khalf ? KCH : 12;
    const uint4* aloc = &g_alo[(size_t)(bid * 8 + msub) * (KCH * 32)];

    // ================= time loop =================
    for (int t = 0; t < TT; ++t) {
        // ---- stage B_hi + B_lo via cp.async ----
        for (int i = tid; i < 32 * 2 * KCH; i += NTHREADS) {
            const int n = i / (2 * KCH), kc = i % (2 * KCH);
            cp_async16(smem_u + SM_BHI + n * (KTPAD * 2) + kc * 16,
                       g_qT_hi + (size_t)n * KPAD + ksl * KSL + kc * 8);
            cp_async16(smem_u + SM_BLO + n * (KTPAD * 2) + kc * 16,
                       g_qT_lo + (size_t)n * KPAD + ksl * KSL + kc * 8);
        }
        asm volatile("cp.async.commit_group;" ::: "memory");
        asm volatile("cp.async.wait_group 0;" ::: "memory");
        __syncthreads();

        // ---- fused 3-term MMA over this warp's k chunks ----
        float D[4][4];
        #pragma unroll
        for (int n = 0; n < 4; n++) { D[n][0] = D[n][1] = D[n][2] = D[n][3] = 0.0f; }

        uint4 alv = __ldcg(&aloc[cbeg * 32 + lane]);
        #pragma unroll 1
        for (int c = cbeg; c < cend; ++c) {
            const uint4 ah = *(const uint4*)(smem + SM_AHI + (size_t)((msub * KCH + c) * 32 + lane) * 16);
            const uint4 al = alv;
            if (c + 1 < cend) alv = __ldcg(&aloc[(c + 1) * 32 + lane]);
            #pragma unroll
            for (int n = 0; n < 4; n++) {
                const char* bph = smem + SM_BHI + (size_t)(n * 8 + g) * (KTPAD * 2)
                                + (size_t)(c * 16 + tig * 2) * 2;
                const char* bpl = smem + SM_BLO + (size_t)(n * 8 + g) * (KTPAD * 2)
                                + (size_t)(c * 16 + tig * 2) * 2;
                const uint32_t bh0 = *(const uint32_t*)bph;
                const uint32_t bh1 = *(const uint32_t*)(bph + 16);
                const uint32_t bl0 = *(const uint32_t*)bpl;
                const uint32_t bl1 = *(const uint32_t*)(bpl + 16);
                MMA_BF16(D[n], ah, bh0, bh1);
                MMA_BF16(D[n], al, bh0, bh1);
                MMA_BF16(D[n], ah, bl0, bl1);
            }
        }

        // ---- accumulate into g_agg via REDG (no gather round-trip) ----
        {
            const int r0g = mtg * 128 + msub * 16 + g;      // rows r0g, r0g+8
            #pragma unroll
            for (int n = 0; n < 4; n++) {
                const int col = n * 8 + tig * 2;
                float* p0 = &g_agg[(size_t)r0g * 32 + col];
                float* p1 = &g_agg[(size_t)(r0g + 8) * 32 + col];
                red_add(p0,     D[n][0]); red_add(p0 + 1, D[n][1]);
                red_add(p1,     D[n][2]); red_add(p1 + 1, D[n][3]);
            }
        }
        grid_barrier(2 + 2 * t);

        // ---- LSTM phase (CTAs 0..124): read agg once, re-zero in place ----
        if (lstm) {
            for (int e = tid; e < ROWS * HH; e += NTHREADS) {
                const int m = e >> 5, n = e & 31;
                float* ap = &g_agg[(size_t)(row0 + m) * 32 + n];
                float aggv;
                asm volatile("ld.global.cg.f32 %0, [%1];" : "=f"(aggv) : "l"(ap));
                asm volatile("st.global.cg.f32 [%0], %1;" :: "l"(ap), "f"(0.0f) : "memory");
                const float iv = g4s[m * G4 + n];
                const float fv = g4s[m * G4 + HH + n];
                const float gv = g4s[m * G4 + 2 * HH + n];
                const float ov = g4s[m * G4 + 3 * HH + n];
                const float cv = fv * (cs[e] + aggv) + iv * gv;
                cs[e] = cv;
                hs[e] = ov * tanh_f(cv);
            }
            if (t + 1 < TT) {
                for (int e = tid; e < ROWS * DD; e += NTHREADS)
                    xs[e] = x[(size_t)(row0 + e / DD) * (TT * DD) + (t + 1) * DD + (e & (DD - 1))];
            }
            __syncthreads();
            if (tid < ROWS) {
                float a = b_d[0];
                #pragma unroll
                for (int n = 0; n < HH; n++) a += hs[tid * HH + n] * W_d[n];
                out[(size_t)(row0 + tid) * TT + t] = a;
            }
            if (t + 1 < TT) {
                gates_act(tid, xs, hs, g4s, W_ih, W_hh, b);
                q_prep(tid, row0, hs, W_q, b_q);
            }
        }
        if (t + 1 < TT) grid_barrier(3 + 2 * t);
    }
}

extern "C" void kernel_launch(void* const* d_in, const int* in_sizes, int n_in,
                              void* d_out, int out_size) {
    (void)in_sizes; (void)n_in; (void)out_size;
    const float* x    = (const float*)d_in[0];
    const float* adj  = (const float*)d_in[1];
    const float* W_ih = (const float*)d_in[2];
    const float* W_hh = (const float*)d_in[3];
    const float* b    = (const float*)d_in[4];
    const float* W_q  = (const float*)d_in[5];
    const float* b_q  = (const float*)d_in[6];
    const float* W_d  = (const float*)d_in[7];
    const float* b_d  = (const float*)d_in[8];
    float* out = (float*)d_out;

    cudaFuncSetAttribute(rgcn_kernel,
                         cudaFuncAttributeMaxDynamicSharedMemorySize, SMEM_TOTAL);
    rgcn_reset<<<1, 1>>>();
    rgcn_kernel<<<NCTA, NTHREADS, SMEM_TOTAL>>>(x, adj, W_ih, W_hh, b,
                                                W_q, b_q, W_d, b_d, out);
}

// round 16
// speedup vs baseline: 1.1207x; 1.1207x over previous
#include <cuda_runtime.h>
#include <cuda_bf16.h>
#include <math.h>
#include <cstdint>

#define BSN 2500
#define TT  400
#define DD  16
#define HH  32
#define G4  128

#define MTILES   20
#define KSLICES  7
#define KSL      368          // 7*368 = 2576 >= 2500
#define KCH      23           // K16 chunks per slice
#define KTPAD    376          // padded k stride in B stage
#define KPAD     2576         // global q^T k stride
#define NCTA     140
#define NTHREADS 512
#define LCTAS    125
#define ROWS     20

// SMEM layout (bytes)
#define AFRAG_BYTES (8*KCH*32*16)              // 94208 (A_hi only)
#define SM_AHI   0
#define SM_BHI   AFRAG_BYTES                   // 94208  (reused as D-merge dump post-MMA)
#define BST_BYTES (32*KTPAD*2)                 // 24064
#define SM_BLO   (SM_BHI + BST_BYTES)          // 118272
#define SM_G4S   (SM_BLO + BST_BYTES)          // 142336
#define SM_HS    (SM_G4S + ROWS*G4*4)          // 152576
#define SM_CS    (SM_HS + ROWS*HH*4)           // 155136
#define SM_XS    (SM_CS + ROWS*HH*4)           // 157696
#define SMEM_TOTAL (SM_XS + ROWS*DD*4 + 64)    // 159040

__device__ unsigned int g_bar;
__device__ unsigned int g_cnt[MTILES];                    // per-mtile arrival counters (monotone)
__device__ __nv_bfloat16 g_qT_hi[2][32 * KPAD];           // parity double-buffered q^T
__device__ __nv_bfloat16 g_qT_lo[2][32 * KPAD];
__device__ uint4 g_alo[(size_t)NCTA * 8 * KCH * 32];      // A_lo fragments
__device__ float g_part[(size_t)NCTA * 128 * 32];         // merged partials per (mtile,kslice)

#define MMA_BF16(d, a, b0_, b1_) \
    asm volatile("mma.sync.aligned.m16n8k16.row.col.f32.bf16.bf16.f32 " \
        "{%0,%1,%2,%3}, {%4,%5,%6,%7}, {%8,%9}, {%0,%1,%2,%3};" \
        : "+f"((d)[0]), "+f"((d)[1]), "+f"((d)[2]), "+f"((d)[3]) \
        : "r"((a).x), "r"((a).y), "r"((a).z), "r"((a).w), "r"(b0_), "r"(b1_))

__device__ __forceinline__ float sigmoid_f(float x) {
    return __fdividef(1.0f, 1.0f + __expf(-x));
}
__device__ __forceinline__ float tanh_f(float x) {
    return 1.0f - __fdividef(2.0f, __expf(2.0f * x) + 1.0f);
}
__device__ __forceinline__ void st_u16_cg(__nv_bfloat16* p, unsigned short v) {
    asm volatile("st.global.cg.u16 [%0], %1;" :: "l"(p), "h"(v) : "memory");
}
__device__ __forceinline__ unsigned ld_acq(const unsigned* p) {
    unsigned v;
    asm volatile("ld.acquire.gpu.global.u32 %0, [%1];" : "=r"(v) : "l"(p) : "memory");
    return v;
}

__device__ __forceinline__ void grid_barrier(unsigned epoch) {
    __threadfence();
    __syncthreads();
    if (threadIdx.x == 0) {
        atomicAdd(&g_bar, 1u);
        const unsigned target = epoch * (unsigned)NCTA;
        while (ld_acq(&g_bar) < target) { }
    }
    __syncthreads();
}

__global__ void rgcn_reset() {
    g_bar = 0u;
    for (int i = 0; i < MTILES; i++) g_cnt[i] = 0u;
}

__device__ __forceinline__ void split_pair(const float* __restrict__ adj, int r, int k,
                                           uint32_t& h, uint32_t& l) {
    float xv = (r < BSN && k     < BSN) ? __ldg(&adj[(size_t)r * BSN + k])     : 0.0f;
    float yv = (r < BSN && k + 1 < BSN) ? __ldg(&adj[(size_t)r * BSN + k + 1]) : 0.0f;
    __nv_bfloat16 hx = __float2bfloat16(xv), hy = __float2bfloat16(yv);
    __nv_bfloat16 lx = __float2bfloat16(xv - __bfloat162float(hx));
    __nv_bfloat16 ly = __float2bfloat16(yv - __bfloat162float(hy));
    h = (uint32_t)__bfloat16_as_ushort(hx) | ((uint32_t)__bfloat16_as_ushort(hy) << 16);
    l = (uint32_t)__bfloat16_as_ushort(lx) | ((uint32_t)__bfloat16_as_ushort(ly) << 16);
}

// gates pre-activated into g4s (512 threads: 4 groups x 5 rows)
__device__ __forceinline__ void gates_act(
    int tid, const float* xs, const float* hs, float* g4s,
    const float* __restrict__ W_ih, const float* __restrict__ W_hh,
    const float* __restrict__ b)
{
    const int j  = tid & 127;
    const int m0 = (tid >> 7) * 5;
    float a5[5];
    const float bj = b[j];
    #pragma unroll
    for (int mm = 0; mm < 5; mm++) a5[mm] = bj;
    #pragma unroll
    for (int kk = 0; kk < HH; kk++) {
        const float w = W_hh[kk * G4 + j];
        #pragma unroll
        for (int mm = 0; mm < 5; mm++) a5[mm] += hs[(m0 + mm) * HH + kk] * w;
    }
    #pragma unroll
    for (int d = 0; d < DD; d++) {
        const float w = W_ih[d * G4 + j];
        #pragma unroll
        for (int mm = 0; mm < 5; mm++) a5[mm] += xs[(m0 + mm) * DD + d] * w;
    }
    const int sect = j >> 5;
    #pragma unroll
    for (int mm = 0; mm < 5; mm++) {
        const float v = (sect == 2) ? tanh_f(a5[mm]) : sigmoid_f(a5[mm]);
        g4s[(m0 + mm) * G4 + j] = v;
    }
}

__device__ __forceinline__ void q_prep(
    int tid, int row0, int buf, const float* hs,
    const float* __restrict__ W_q, const float* __restrict__ b_q)
{
    for (int e = tid; e < ROWS * HH; e += NTHREADS) {
        const int m = e >> 5, n = e & 31;
        float a = b_q[n];
        #pragma unroll
        for (int kk = 0; kk < HH; kk++) a += hs[m * HH + kk] * W_q[kk * HH + n];
        const float q = tanh_f(a);
        const __nv_bfloat16 hi = __float2bfloat16(q);
        const __nv_bfloat16 lo = __float2bfloat16(q - __bfloat162float(hi));
        const int r = row0 + m;
        st_u16_cg(&g_qT_hi[buf][n * KPAD + r], __bfloat16_as_ushort(hi));
        st_u16_cg(&g_qT_lo[buf][n * KPAD + r], __bfloat16_as_ushort(lo));
    }
}

__global__ void __launch_bounds__(NTHREADS, 1)
rgcn_kernel(const float* __restrict__ x,    const float* __restrict__ adj,
            const float* __restrict__ W_ih, const float* __restrict__ W_hh,
            const float* __restrict__ b,    const float* __restrict__ W_q,
            const float* __restrict__ b_q,  const float* __restrict__ W_d,
            const float* __restrict__ b_d,  float* __restrict__ out)
{
    extern __shared__ char smem[];
    float* g4s  = (float*)(smem + SM_G4S);
    float* hs   = (float*)(smem + SM_HS);
    float* cs   = (float*)(smem + SM_CS);
    float* xs   = (float*)(smem + SM_XS);
    float* dump = (float*)(smem + SM_BHI);   // reused post-MMA: [8 msub][16 rows][32 cols]

    const int tid  = threadIdx.x;
    const int lane = tid & 31;
    const int wid  = tid >> 5;
    const int bid  = blockIdx.x;
    const int mtg  = bid / KSLICES;
    const int ksl  = bid % KSLICES;
    const bool lstm = (bid < LCTAS);
    const int row0 = bid * ROWS;
    const int g    = lane >> 2;
    const int tig  = lane & 3;
    const int msub  = wid & 7;
    const int khalf = wid >> 3;

    // mtile counters this LSTM CTA depends on (rows may straddle 2 mtiles)
    const int mtr_lo = (row0) >> 7;
    const int mtr_hi = (row0 + ROWS - 1) >> 7;

    // ---- prologue: A_hi frags -> SMEM, A_lo frags -> global ----
    for (int idx = tid; idx < 8 * KCH * 32; idx += NTHREADS) {
        const int l  = idx & 31;
        const int c  = (idx >> 5) % KCH;
        const int mt = idx / (KCH * 32);
        const int lg = l >> 2, lt = l & 3;
        const int r0 = mtg * 128 + mt * 16 + lg;
        const int kb = ksl * KSL + c * 16 + lt * 2;
        uint32_t h0, h1, h2, h3, l0, l1, l2, l3;
        split_pair(adj, r0,     kb,     h0, l0);
        split_pair(adj, r0 + 8, kb,     h1, l1);
        split_pair(adj, r0,     kb + 8, h2, l2);
        split_pair(adj, r0 + 8, kb + 8, h3, l3);
        *(uint4*)(smem + SM_AHI + (size_t)idx * 16) = make_uint4(h0, h1, h2, h3);
        g_alo[(size_t)bid * (8 * KCH * 32) + idx] = make_uint4(l0, l1, l2, l3);
    }

    if (lstm) {
        for (int e = tid; e < ROWS * HH; e += NTHREADS) { hs[e] = 0.0f; cs[e] = 0.0f; }
        for (int e = tid; e < ROWS * DD; e += NTHREADS)
            xs[e] = x[(size_t)(row0 + e / DD) * (TT * DD) + (e & (DD - 1))];
    }
    __syncthreads();
    if (lstm) {
        gates_act(tid, xs, hs, g4s, W_ih, W_hh, b);
        q_prep(tid, row0, 0, hs, W_q, b_q);
    }
    grid_barrier(1);

    const int cbeg = khalf ? 12 : 0;
    const int cend = khalf ? KCH : 12;
    const uint4* aloc = &g_alo[(size_t)(bid * 8 + msub) * (KCH * 32)];

    // ================= time loop (ONE grid barrier per step) =================
    for (int t = 0; t < TT; ++t) {
        const __nv_bfloat16* qh = g_qT_hi[t & 1];
        const __nv_bfloat16* ql = g_qT_lo[t & 1];

        // ---- stage B_hi + B_lo (LDG.cg -> STS) ----
        for (int i = tid; i < 32 * 2 * KCH; i += NTHREADS) {
            const int n = i / (2 * KCH), kc = i % (2 * KCH);
            const uint4 vh = __ldcg((const uint4*)(qh + (size_t)n * KPAD + ksl * KSL + kc * 8));
            const uint4 vl = __ldcg((const uint4*)(ql + (size_t)n * KPAD + ksl * KSL + kc * 8));
            *(uint4*)(smem + SM_BHI + (size_t)n * (KTPAD * 2) + kc * 16) = vh;
            *(uint4*)(smem + SM_BLO + (size_t)n * (KTPAD * 2) + kc * 16) = vl;
        }
        __syncthreads();

        // ---- fused 3-term MMA over this warp's k chunks ----
        float D[4][4];
        #pragma unroll
        for (int n = 0; n < 4; n++) { D[n][0] = D[n][1] = D[n][2] = D[n][3] = 0.0f; }

        uint4 alv = __ldcg(&aloc[cbeg * 32 + lane]);
        #pragma unroll 1
        for (int c = cbeg; c < cend; ++c) {
            const uint4 ah = *(const uint4*)(smem + SM_AHI + (size_t)((msub * KCH + c) * 32 + lane) * 16);
            const uint4 al = alv;
            if (c + 1 < cend) alv = __ldcg(&aloc[(c + 1) * 32 + lane]);
            #pragma unroll
            for (int n = 0; n < 4; n++) {
                const char* bph = smem + SM_BHI + (size_t)(n * 8 + g) * (KTPAD * 2)
                                + (size_t)(c * 16 + tig * 2) * 2;
                const char* bpl = smem + SM_BLO + (size_t)(n * 8 + g) * (KTPAD * 2)
                                + (size_t)(c * 16 + tig * 2) * 2;
                const uint32_t bh0 = *(const uint32_t*)bph;
                const uint32_t bh1 = *(const uint32_t*)(bph + 16);
                const uint32_t bl0 = *(const uint32_t*)bpl;
                const uint32_t bl1 = *(const uint32_t*)(bpl + 16);
                MMA_BF16(D[n], ah, bh0, bh1);
                MMA_BF16(D[n], al, bh0, bh1);
                MMA_BF16(D[n], ah, bl0, bl1);
            }
        }
        __syncthreads();   // B fully consumed -> dump region free

        // ---- khalf merge: khalf=1 dumps D to SMEM, khalf=0 adds + stores ----
        if (khalf == 1) {
            #pragma unroll
            for (int n = 0; n < 4; n++) {
                const int col = n * 8 + tig * 2;
                dump[(msub * 16 + g)     * 32 + col]     = D[n][0];
                dump[(msub * 16 + g)     * 32 + col + 1] = D[n][1];
                dump[(msub * 16 + g + 8) * 32 + col]     = D[n][2];
                dump[(msub * 16 + g + 8) * 32 + col + 1] = D[n][3];
            }
        }
        __syncthreads();
        if (khalf == 0) {
            float* pb = g_part + ((size_t)bid * 128 + msub * 16 + g) * 32;
            #pragma unroll
            for (int n = 0; n < 4; n++) {
                const int col = n * 8 + tig * 2;
                const float v0 = D[n][0] + dump[(msub * 16 + g)     * 32 + col];
                const float v1 = D[n][1] + dump[(msub * 16 + g)     * 32 + col + 1];
                const float v2 = D[n][2] + dump[(msub * 16 + g + 8) * 32 + col];
                const float v3 = D[n][3] + dump[(msub * 16 + g + 8) * 32 + col + 1];
                __stcg((float2*)(pb + col),          make_float2(v0, v1));
                __stcg((float2*)(pb + 8 * 32 + col), make_float2(v2, v3));
            }
        }
        __threadfence();
        __syncthreads();
        if (tid == 0) atomicAdd(&g_cnt[mtg], 1u);   // signal this mtile's partials ready

        // ---- LSTM phase: wait only on OUR mtile counters, then update ----
        if (lstm) {
            if (tid == 0) {
                const unsigned target = (unsigned)(KSLICES * (t + 1));
                while (ld_acq(&g_cnt[mtr_lo]) < target) { }
                if (mtr_hi != mtr_lo)
                    while (ld_acq(&g_cnt[mtr_hi]) < target) { }
            }
            __syncthreads();
            for (int e = tid; e < ROWS * HH; e += NTHREADS) {
                const int m = e >> 5, n = e & 31;
                const int r = row0 + m;
                const int mtr = r >> 7, mr = r & 127;
                float aggv = 0.0f;
                #pragma unroll
                for (int s = 0; s < KSLICES; s++)
                    aggv += __ldcg(&g_part[(((size_t)mtr * KSLICES + s) * 128 + mr) * 32 + n]);
                const float iv = g4s[m * G4 + n];
                const float fv = g4s[m * G4 + HH + n];
                const float gv = g4s[m * G4 + 2 * HH + n];
                const float ov = g4s[m * G4 + 3 * HH + n];
                const float cv = fv * (cs[e] + aggv) + iv * gv;
                cs[e] = cv;
                hs[e] = ov * tanh_f(cv);
            }
            if (t + 1 < TT) {
                for (int e = tid; e < ROWS * DD; e += NTHREADS)
                    xs[e] = x[(size_t)(row0 + e / DD) * (TT * DD) + (t + 1) * DD + (e & (DD - 1))];
            }
            __syncthreads();
            if (tid < ROWS) {
                float a = b_d[0];
                #pragma unroll
                for (int n = 0; n < HH; n++) a += hs[tid * HH + n] * W_d[n];
                out[(size_t)(row0 + tid) * TT + t] = a;
            }
            if (t + 1 < TT) {
                gates_act(tid, xs, hs, g4s, W_ih, W_hh, b);
                q_prep(tid, row0, (t + 1) & 1, hs, W_q, b_q);
            }
        }

        // single barrier per step: q_{t+1} + partial-slot recycling both ordered here
        if (t + 1 < TT) grid_barrier((unsigned)(t + 2));
    }
}

extern "C" void kernel_launch(void* const* d_in, const int* in_sizes, int n_in,
                              void* d_out, int out_size) {
    (void)in_sizes; (void)n_in; (void)out_size;
    const float* x    = (const float*)d_in[0];
    const float* adj  = (const float*)d_in[1];
    const float* W_ih = (const float*)d_in[2];
    const float* W_hh = (const float*)d_in[3];
    const float* b    = (const float*)d_in[4];
    const float* W_q  = (const float*)d_in[5];
    const float* b_q  = (const float*)d_in[6];
    const float* W_d  = (const float*)d_in[7];
    const float* b_d  = (const float*)d_in[8];
    float* out = (float*)d_out;

    cudaFuncSetAttribute(rgcn_kernel,
                         cudaFuncAttributeMaxDynamicSharedMemorySize, SMEM_TOTAL);
    rgcn_reset<<<1, 1>>>();
    rgcn_kernel<<<NCTA, NTHREADS, SMEM_TOTAL>>>(x, adj, W_ih, W_hh, b,
                                                W_q, b_q, W_d, b_d, out);
}